// round 2
// baseline (speedup 1.0000x reference)
#include <cuda_runtime.h>
#include <cstdint>

// FConvLayer: irfft(rfft(x)*rfft(w_pad)) with ortho norm == circular conv / sqrt(S).
// y[b,t,h] = (1/64) * sum_{k<16} w[k,h] * x[b,(t-k) mod 4096,h]
// out = LayerNorm_H(y + x) * ln_w + ln_b
//
// Design: register sliding-window depthwise conv, no shared memory.
//  - 1 warp = one 128-row t-strip of one batch; lane l owns h in [4l, 4l+4).
//  - 16-row history ring in registers (f32x2 pairs), weights pre-scaled by 1/64
//    in registers, 8-deep global prefetch queue for DRAM latency hiding.
//  - packed fma.rn.f32x2 halves FMA-pipe pressure vs scalar FFMA.
//  - LayerNorm: warp butterfly reduce of sum / sumsq over the 128 hidden values.

typedef unsigned long long u64;
#define DINL __device__ __forceinline__

DINL u64 pack2(float lo, float hi) {
    u64 r; asm("mov.b64 %0, {%1,%2};" : "=l"(r) : "f"(lo), "f"(hi)); return r;
}
DINL void unpack2(u64 v, float& lo, float& hi) {
    asm("mov.b64 {%0,%1}, %2;" : "=f"(lo), "=f"(hi) : "l"(v));
}
DINL u64 fma2(u64 a, u64 b, u64 c) {
    u64 d; asm("fma.rn.f32x2 %0,%1,%2,%3;" : "=l"(d) : "l"(a), "l"(b), "l"(c)); return d;
}
DINL u64 add2(u64 a, u64 b) {
    u64 d; asm("add.rn.f32x2 %0,%1,%2;" : "=l"(d) : "l"(a), "l"(b)); return d;
}
DINL u64 sub2(u64 a, u64 b) {
    u64 d; asm("sub.rn.f32x2 %0,%1,%2;" : "=l"(d) : "l"(a), "l"(b)); return d;
}
DINL u64 mul2(u64 a, u64 b) {
    u64 d; asm("mul.rn.f32x2 %0,%1,%2;" : "=l"(d) : "l"(a), "l"(b)); return d;
}

constexpr int S_LEN = 4096;
constexpr int H_DIM = 128;
constexpr int K_SZ  = 16;
constexpr int LROWS = 128;   // rows per warp strip (t0 multiple of 128)
constexpr int PF    = 8;     // prefetch depth (divides 16)
constexpr int ROW_V = H_DIM / 4;  // 32 ulonglong2 per row

__global__ void __launch_bounds__(128, 2) fconv_ln_kernel(
    const float* __restrict__ x,
    const float* __restrict__ cw,
    const float* __restrict__ lnw,
    const float* __restrict__ lnb,
    float* __restrict__ out)
{
    const int lane  = threadIdx.x & 31;
    const int gwarp = (blockIdx.x * blockDim.x + threadIdx.x) >> 5;
    const int spb   = S_LEN / LROWS;           // strips per batch = 32
    const int b     = gwarp / spb;
    const int t0    = (gwarp % spb) * LROWS;

    const ulonglong2* __restrict__ xb =
        reinterpret_cast<const ulonglong2*>(x) + (size_t)b * S_LEN * ROW_V;
    ulonglong2* __restrict__ ob =
        reinterpret_cast<ulonglong2*>(out) + (size_t)b * S_LEN * ROW_V;

    // ---- weights, pre-scaled by 1/sqrt(S) = 1/64, held as f32x2 pairs ----
    u64 w[K_SZ][2];
    {
        const ulonglong2* cw2 = reinterpret_cast<const ulonglong2*>(cw);
        const u64 sc2 = pack2(0.015625f, 0.015625f);
#pragma unroll
        for (int k = 0; k < K_SZ; k++) {
            ulonglong2 v = cw2[k * ROW_V + lane];
            w[k][0] = mul2(v.x, sc2);
            w[k][1] = mul2(v.y, sc2);
        }
    }

    // ---- LN params for this lane's 4 hidden channels ----
    u64 lw[2], lb[2];
    {
        ulonglong2 v = reinterpret_cast<const ulonglong2*>(lnw)[lane];
        lw[0] = v.x; lw[1] = v.y;
        ulonglong2 u = reinterpret_cast<const ulonglong2*>(lnb)[lane];
        lb[0] = u.x; lb[1] = u.y;
    }

    // ---- history ring: slot s holds row r with r == s (mod 16) ----
    u64 hist[K_SZ][2];
#pragma unroll
    for (int i = 1; i < K_SZ; i++) {
        int r = (t0 - K_SZ + i + S_LEN) & (S_LEN - 1);
        ulonglong2 v = xb[r * ROW_V + lane];
        hist[i][0] = v.x; hist[i][1] = v.y;
    }

    // ---- prefetch queue ----
    ulonglong2 pf[PF];
#pragma unroll
    for (int q = 0; q < PF; q++) {
        int r = (t0 + q) & (S_LEN - 1);
        pf[q] = xb[r * ROW_V + lane];
    }

#pragma unroll 1
    for (int tc = t0; tc < t0 + LROWS; tc += K_SZ) {
#pragma unroll
        for (int j = 0; j < K_SZ; j++) {
            // consume prefetched row (tc+j), refill queue with row (tc+j+PF)
            ulonglong2 cur = pf[j & (PF - 1)];
            hist[j][0] = cur.x;
            hist[j][1] = cur.y;
            {
                int r = (tc + j + PF) & (S_LEN - 1);
                pf[j & (PF - 1)] = xb[r * ROW_V + lane];
            }

            // depthwise circular conv: y = sum_k w[k] * x[t-k]
            u64 a0 = 0ull, a1 = 0ull;  // +0.0f pairs
#pragma unroll
            for (int k = 0; k < K_SZ; k++) {
                const int s = (j - k) & (K_SZ - 1);
                a0 = fma2(w[k][0], hist[s][0], a0);
                a1 = fma2(w[k][1], hist[s][1], a1);
            }

            // residual
            u64 h0 = add2(a0, hist[j][0]);
            u64 h1 = add2(a1, hist[j][1]);

            // LayerNorm over 128 hidden values (warp = full row)
            float f0, f1, f2, f3;
            unpack2(h0, f0, f1);
            unpack2(h1, f2, f3);
            float s  = (f0 + f1) + (f2 + f3);
            float sq = fmaf(f0, f0, fmaf(f1, f1, fmaf(f2, f2, f3 * f3)));
#pragma unroll
            for (int off = 16; off > 0; off >>= 1) {
                s  += __shfl_xor_sync(0xffffffffu, s,  off);
                sq += __shfl_xor_sync(0xffffffffu, sq, off);
            }
            const float mean = s * (1.0f / 128.0f);
            float var = fmaf(sq, 1.0f / 128.0f, -mean * mean);
            var = fmaxf(var, 0.0f);
            const float inv = rsqrtf(var + 1e-12f);

            const u64 inv2  = pack2(inv, inv);
            const u64 mean2 = pack2(mean, mean);
            u64 o0 = fma2(mul2(sub2(h0, mean2), inv2), lw[0], lb[0]);
            u64 o1 = fma2(mul2(sub2(h1, mean2), inv2), lw[1], lb[1]);

            ulonglong2 ov;
            ov.x = o0; ov.y = o1;
            ob[(tc + j) * ROW_V + lane] = ov;
        }
    }
}

extern "C" void kernel_launch(void* const* d_in, const int* in_sizes, int n_in,
                              void* d_out, int out_size)
{
    const float* x   = (const float*)d_in[0];  // [64, 4096, 128]
    const float* cw  = (const float*)d_in[1];  // [1, 16, 128]
    const float* lnw = (const float*)d_in[2];  // [128]
    const float* lnb = (const float*)d_in[3];  // [128]
    float* out = (float*)d_out;                // [64, 4096, 128]

    // total warps = 64 batches * 32 strips = 2048; 4 warps/block -> 512 blocks
    const int total_warps = 64 * (S_LEN / LROWS);
    const int blocks = total_warps / 4;
    fconv_ln_kernel<<<blocks, 128>>>(x, cw, lnw, lnb, out);
}